// round 14
// baseline (speedup 1.0000x reference)
#include <cuda_runtime.h>
#include <math.h>
#include <stdint.h>

#define HD 32
#define MAXN 10000
#define CAP 256      // max in-degree supported (E/N = 32 mean; Poisson tail << 256)

// Scratch (device globals — no allocation allowed; zero-initialized at load)
__device__ float g_z[MAXN * HD];
__device__ float g_u[MAXN * HD];
__device__ float g_v[MAXN * HD];
__device__ float g_pa[MAXN];
__device__ float g_pb[MAXN];
__device__ float g_hsum[HD];
__device__ int   g_cnt[MAXN];     // zero at load; reset by k_rowfill each call
__device__ int2  g_list[MAXN * CAP];   // packed edge payload: {source, weight_bits}
__device__ int   g_upd_ticket;    // single-kernel ticket; reset by last update block

// ---------------------------------------------------------------------------
// Grid-stride streaming fill of rows [rowBeg, rowEnd) of p with -1e9.
// Called from the TAIL of chain kernels: soaks idle DRAM-store bandwidth
// while the latency-bound chain work dominates the critical path.
// ---------------------------------------------------------------------------
__device__ __forceinline__ void fill_rows(float* __restrict__ p, int rowBeg, int rowEnd, int N) {
    if (rowEnd <= rowBeg) return;
    size_t stride = (size_t)gridDim.x * blockDim.x;
    size_t start  = (size_t)blockIdx.x * blockDim.x + threadIdx.x;
    size_t nflt   = (size_t)(rowEnd - rowBeg) * (size_t)N;
    float* base   = p + (size_t)rowBeg * (size_t)N;
    if ((N & 3) == 0) {
        const float4 val = make_float4(-1e9f, -1e9f, -1e9f, -1e9f);
        float4* p4 = (float4*)base;
        size_t n4 = nflt >> 2;
        for (size_t i = start; i < n4; i += stride) __stcs(&p4[i], val);
    } else {
        for (size_t i = start; i < nflt; i += stride) __stcs(&base[i], -1e9f);
    }
}

// ---------------------------------------------------------------------------
// Build per-dest edge lists with PACKED payload (s, w). Block 0 zeroes g_hsum.
// Tail: fill rows [0, c1).
// ---------------------------------------------------------------------------
__global__ void k_build(const int* __restrict__ dests, const int* __restrict__ sources,
                        const float* __restrict__ weights, int E,
                        float* __restrict__ p, int c1, int N) {
    int tid = threadIdx.x;
    if (blockIdx.x == 0 && tid < HD) g_hsum[tid] = 0.0f;
    int e = blockIdx.x * blockDim.x + tid;
    if (e < E) {
        int d = dests[e];
        int s = sources[e];                 // coalesced
        float w = weights[e];               // coalesced
        int slot = atomicAdd(&g_cnt[d], 1);
        if (slot < CAP) g_list[d * CAP + slot] = make_int2(s, __float_as_int(w));
    }
    fill_rows(p, 0, c1, N);
}

// ---------------------------------------------------------------------------
// Encoder: z = [x,h]@W_enc + b_enc; u = z@W_msg[0:32], v = z@W_msg[32:64].
// Warp per node, lane = feature. Tail: fill rows [c1, c2).
// ---------------------------------------------------------------------------
__global__ void k_encoder(const float* __restrict__ x, const float* __restrict__ h,
                          const float* __restrict__ W_enc, const float* __restrict__ b_enc,
                          const float* __restrict__ W_msg, int N,
                          float* __restrict__ p, int c1, int c2) {
    __shared__ float sWe[33 * HD];
    __shared__ float sWm[64 * HD];
    int tid = threadIdx.x;
    for (int i = tid; i < 33 * HD; i += blockDim.x) sWe[i] = W_enc[i];
    for (int i = tid; i < 64 * HD; i += blockDim.x) sWm[i] = W_msg[i];
    __syncthreads();

    int lane = tid & 31;
    int node = (int)((blockIdx.x * (size_t)blockDim.x + tid) >> 5);
    if (node < N) {
        float xn = x[node];
        float hl = h[node * HD + lane];
        float z0 = fmaf(xn, sWe[lane], b_enc[lane]);
        float z1 = 0.0f;
#pragma unroll
        for (int k = 0; k < HD; k += 2) {
            float hk0 = __shfl_sync(0xffffffffu, hl, k);
            float hk1 = __shfl_sync(0xffffffffu, hl, k + 1);
            z0 = fmaf(hk0, sWe[(1 + k) * HD + lane], z0);
            z1 = fmaf(hk1, sWe[(2 + k) * HD + lane], z1);
        }
        float z = z0 + z1;
        g_z[node * HD + lane] = z;

        float u = 0.0f, v = 0.0f;
#pragma unroll
        for (int k = 0; k < HD; k++) {
            float zk = __shfl_sync(0xffffffffu, z, k);
            u = fmaf(zk, sWm[k * HD + lane], u);
            v = fmaf(zk, sWm[(HD + k) * HD + lane], v);
        }
        g_u[node * HD + lane] = u;
        g_v[node * HD + lane] = v;
    }
    fill_rows(p, c1, c2, N);
}

// ---------------------------------------------------------------------------
// Update: segment-max over packed edge payload (8-wide MLP gathers) + decode
// + pred scalars + hsum. Warp per node. Last block (ticket) computes the
// termination scalar. Tail: fill rows [c2, c3).
// ---------------------------------------------------------------------------
__global__ void k_update(const float* __restrict__ W_msg, const float* __restrict__ b_msg,
                         const float* __restrict__ W_upd, const float* __restrict__ b_upd,
                         const float* __restrict__ W_dec, const float* __restrict__ b_dec,
                         const float* __restrict__ W_pred,
                         const float* __restrict__ W_term, const float* __restrict__ b_term,
                         float* __restrict__ out_y, float* __restrict__ out_h,
                         float* __restrict__ out_t, int N,
                         float* __restrict__ p, int c2, int c3) {
    __shared__ float sWu[64 * HD];
    __shared__ float red[8][HD];
    __shared__ int sIsLast;
    int tid = threadIdx.x;
    for (int i = tid; i < 64 * HD; i += blockDim.x) sWu[i] = W_upd[i];
    __syncthreads();

    int lane = tid & 31;
    int wip  = tid >> 5;
    int node = (int)((blockIdx.x * (size_t)blockDim.x + tid) >> 5);
    bool act = node < N;
    float hn = 0.0f;

    if (act) {
        float cw = W_msg[64 * HD + lane];
        int cnt = min(g_cnt[node], CAP);
        const int2* lst = &g_list[node * CAP];

        float mraw = __int_as_float(0xFF800000);  // -inf
        for (int base = 0; base < cnt; base += 32) {
            int nrem = min(32, cnt - base);
            int   myS = 0;
            float myW = 0.0f;
            if (lane < nrem) {
                int2 pk = lst[base + lane];   // ONE coalesced 256B load
                myS = pk.x;
                myW = __int_as_float(pk.y);
            }
            int k = 0;
            for (; k + 8 <= nrem; k += 8) {
                int s0 = __shfl_sync(0xffffffffu, myS, k);
                int s1 = __shfl_sync(0xffffffffu, myS, k + 1);
                int s2 = __shfl_sync(0xffffffffu, myS, k + 2);
                int s3 = __shfl_sync(0xffffffffu, myS, k + 3);
                int s4 = __shfl_sync(0xffffffffu, myS, k + 4);
                int s5 = __shfl_sync(0xffffffffu, myS, k + 5);
                int s6 = __shfl_sync(0xffffffffu, myS, k + 6);
                int s7 = __shfl_sync(0xffffffffu, myS, k + 7);
                float w0 = __shfl_sync(0xffffffffu, myW, k);
                float w1 = __shfl_sync(0xffffffffu, myW, k + 1);
                float w2 = __shfl_sync(0xffffffffu, myW, k + 2);
                float w3 = __shfl_sync(0xffffffffu, myW, k + 3);
                float w4 = __shfl_sync(0xffffffffu, myW, k + 4);
                float w5 = __shfl_sync(0xffffffffu, myW, k + 5);
                float w6 = __shfl_sync(0xffffffffu, myW, k + 6);
                float w7 = __shfl_sync(0xffffffffu, myW, k + 7);
                float v0 = g_v[s0 * HD + lane];   // 8 independent row gathers -> MLP 8
                float v1 = g_v[s1 * HD + lane];
                float v2 = g_v[s2 * HD + lane];
                float v3 = g_v[s3 * HD + lane];
                float v4 = g_v[s4 * HD + lane];
                float v5 = g_v[s5 * HD + lane];
                float v6 = g_v[s6 * HD + lane];
                float v7 = g_v[s7 * HD + lane];
                float a = fmaxf(fmaf(w0, cw, v0), fmaf(w1, cw, v1));
                float b = fmaxf(fmaf(w2, cw, v2), fmaf(w3, cw, v3));
                float c = fmaxf(fmaf(w4, cw, v4), fmaf(w5, cw, v5));
                float d = fmaxf(fmaf(w6, cw, v6), fmaf(w7, cw, v7));
                mraw = fmaxf(mraw, fmaxf(fmaxf(a, b), fmaxf(c, d)));
            }
            for (; k < nrem; k++) {
                int   sk = __shfl_sync(0xffffffffu, myS, k);
                float wk = __shfl_sync(0xffffffffu, myW, k);
                mraw = fmaxf(mraw, fmaf(wk, cw, g_v[sk * HD + lane]));
            }
        }

        float z = g_z[node * HD + lane];
        float m = (cnt == 0) ? 0.0f
                             : (g_u[node * HD + lane] + b_msg[lane] + mraw);

        float h0 = b_upd[lane], h1 = 0.0f;
#pragma unroll
        for (int k = 0; k < HD; k++) {
            float zk = __shfl_sync(0xffffffffu, z, k);
            float mk = __shfl_sync(0xffffffffu, m, k);
            h0 = fmaf(zk, sWu[k * HD + lane], h0);
            h1 = fmaf(mk, sWu[(HD + k) * HD + lane], h1);
        }
        hn = h0 + h1;
        out_h[node * HD + lane] = hn;

        float ry = fmaf(z, W_dec[lane], hn * W_dec[HD + lane]);
        float ra = hn * W_pred[lane];
        float rb = hn * W_pred[HD + lane];
#pragma unroll
        for (int o = 16; o > 0; o >>= 1) {
            ry += __shfl_xor_sync(0xffffffffu, ry, o);
            ra += __shfl_xor_sync(0xffffffffu, ra, o);
            rb += __shfl_xor_sync(0xffffffffu, rb, o);
        }
        if (lane == 0) {
            out_y[node] = ry + b_dec[0];
            g_pa[node] = ra;
            g_pb[node] = rb;
        }
    }

    red[wip][lane] = act ? hn : 0.0f;
    __syncthreads();
    if (wip == 0) {
        float s = red[0][lane];
#pragma unroll
        for (int j = 1; j < 8; j++) s += red[j][lane];
        atomicAdd(&g_hsum[lane], s);
    }

    // last-block ticket (same kernel -> all blocks guaranteed to run)
    __syncthreads();
    if (tid == 0) {
        __threadfence();
        int t = atomicAdd(&g_upd_ticket, 1);
        sIsLast = (t == (int)gridDim.x - 1);
    }
    __syncthreads();
    if (sIsLast) {
        if (tid < 32) {
            float v = (__ldcg(&g_hsum[tid]) / (float)N) * W_term[tid];
#pragma unroll
            for (int o = 16; o > 0; o >>= 1) v += __shfl_xor_sync(0xffffffffu, v, o);
            if (tid == 0) {
                out_t[0] = v + b_term[0];
                g_upd_ticket = 0;   // reset for next call
            }
        }
    }

    fill_rows(p, c2, c3, N);
}

// ---------------------------------------------------------------------------
// Final kernel: one block per row. Rows >= PRE: fill + scatter. Rows < PRE
// (already filled by earlier kernels): scatter only. Resets g_cnt.
// ---------------------------------------------------------------------------
__global__ void __launch_bounds__(256)
k_rowfill(const float* __restrict__ W_pred, const float* __restrict__ b_pred,
          float* __restrict__ p, int N, int PRE) {
    int d = blockIdx.x;
    int tid = threadIdx.x;
    float* row = p + (size_t)d * N;

    if (d >= PRE) {
        int n4 = N >> 2;
        const float4 val = make_float4(-1e9f, -1e9f, -1e9f, -1e9f);
        float4* row4 = (float4*)row;
        for (int i = tid; i < n4; i += blockDim.x) __stcs(&row4[i], val);
        for (int i = (n4 << 2) + tid; i < N; i += blockDim.x) __stcs(&row[i], -1e9f);
        __syncthreads();   // row fully filled before edge overwrites
    }

    int cnt = min(g_cnt[d], CAP);
    if (tid < cnt) {
        float pa = g_pa[d];
        float c  = W_pred[64];
        float b0 = b_pred[0];
        for (int i = tid; i < cnt; i += blockDim.x) {
            int2 pk = g_list[d * CAP + i];
            int s = pk.x;
            row[s] = pa + g_pb[s] + fmaf(__int_as_float(pk.y), c, b0);
        }
    }
    if (tid == 0) g_cnt[d] = 0;   // reset for next call
}

// ---------------------------------------------------------------------------
extern "C" void kernel_launch(void* const* d_in, const int* in_sizes, int n_in,
                              void* d_out, int out_size) {
    const int*   sources = (const int*)d_in[0];
    const int*   dests   = (const int*)d_in[1];
    const float* weights = (const float*)d_in[2];
    const float* x       = (const float*)d_in[3];
    const float* h       = (const float*)d_in[4];
    const float* W_enc   = (const float*)d_in[5];
    const float* b_enc   = (const float*)d_in[6];
    const float* W_msg   = (const float*)d_in[7];
    const float* b_msg   = (const float*)d_in[8];
    const float* W_upd   = (const float*)d_in[9];
    const float* b_upd   = (const float*)d_in[10];
    const float* W_dec   = (const float*)d_in[11];
    const float* b_dec   = (const float*)d_in[12];
    const float* W_term  = (const float*)d_in[13];
    const float* b_term  = (const float*)d_in[14];
    const float* W_pred  = (const float*)d_in[15];
    const float* b_pred  = (const float*)d_in[16];

    int E = in_sizes[0];
    int N = in_sizes[3];  // x is (N, 1)

    float* out   = (float*)d_out;
    float* out_y = out;
    float* out_p = out + N;
    float* out_h = out + N + (size_t)N * N;
    float* out_t = out_h + (size_t)N * HD;

    int EB = (E + 255) / 256;
    int NB = (N * 32 + 255) / 256;

    // Fill-slice boundaries, sized to each chain kernel's measured span:
    // build ~8.5% of rows, encoder ~17.5%, update ~28.5% -> 54.5% pre-filled.
    int c1 = (int)((long long)N * 85  / 1000);
    int c2 = c1 + (int)((long long)N * 175 / 1000);
    int c3 = c2 + (int)((long long)N * 285 / 1000);

    k_build<<<EB, 256>>>(dests, sources, weights, E, out_p, c1, N);
    k_encoder<<<NB, 256>>>(x, h, W_enc, b_enc, W_msg, N, out_p, c1, c2);
    k_update<<<NB, 256>>>(W_msg, b_msg, W_upd, b_upd,
                          W_dec, b_dec, W_pred, W_term, b_term,
                          out_y, out_h, out_t, N, out_p, c2, c3);
    k_rowfill<<<N, 256>>>(W_pred, b_pred, out_p, N, c3);
}

// round 15
// speedup vs baseline: 1.0373x; 1.0373x over previous
#include <cuda_runtime.h>
#include <math.h>
#include <stdint.h>

#define HD 32
#define MAXN 10000
#define CAP 256      // max in-degree supported (E/N = 32 mean; Poisson tail << 256)

// Scratch (device globals — no allocation allowed; zero-initialized at load)
__device__ float g_z[MAXN * HD];
__device__ float g_u[MAXN * HD];
__device__ float g_v[MAXN * HD];
__device__ float g_pa[MAXN];
__device__ float g_pb[MAXN];
__device__ float g_hsum[HD];
__device__ int   g_cnt[MAXN];     // zero at load; reset by k_rowfill each call
__device__ int2  g_list[MAXN * CAP];   // packed edge payload: {source, weight_bits}
__device__ int   g_upd_ticket;    // single-kernel ticket; reset by last update block

// ---------------------------------------------------------------------------
// Grid-stride streaming fill of rows [rowBeg, rowEnd) of p with -1e9.
// Called from the TAIL of chain kernels; slice sized so fill time fits within
// the kernel's chain span (fill stays hidden, never binding).
// ---------------------------------------------------------------------------
__device__ __forceinline__ void fill_rows(float* __restrict__ p, int rowBeg, int rowEnd, int N) {
    if (rowEnd <= rowBeg) return;
    size_t stride = (size_t)gridDim.x * blockDim.x;
    size_t start  = (size_t)blockIdx.x * blockDim.x + threadIdx.x;
    size_t nflt   = (size_t)(rowEnd - rowBeg) * (size_t)N;
    float* base   = p + (size_t)rowBeg * (size_t)N;
    if ((N & 3) == 0) {
        const float4 val = make_float4(-1e9f, -1e9f, -1e9f, -1e9f);
        float4* p4 = (float4*)base;
        size_t n4 = nflt >> 2;
        for (size_t i = start; i < n4; i += stride) __stcs(&p4[i], val);
    } else {
        for (size_t i = start; i < nflt; i += stride) __stcs(&base[i], -1e9f);
    }
}

// ---------------------------------------------------------------------------
// Build per-dest edge lists with PACKED payload (s, w). Block 0 zeroes g_hsum.
// No fill tail (atomic-heavy, short span).
// ---------------------------------------------------------------------------
__global__ void k_build(const int* __restrict__ dests, const int* __restrict__ sources,
                        const float* __restrict__ weights, int E) {
    int tid = threadIdx.x;
    if (blockIdx.x == 0 && tid < HD) g_hsum[tid] = 0.0f;
    int e = blockIdx.x * blockDim.x + tid;
    if (e >= E) return;
    int d = dests[e];
    int s = sources[e];                 // coalesced
    float w = weights[e];               // coalesced
    int slot = atomicAdd(&g_cnt[d], 1);
    if (slot < CAP) g_list[d * CAP + slot] = make_int2(s, __float_as_int(w));
}

// ---------------------------------------------------------------------------
// Encoder: z = [x,h]@W_enc + b_enc; u = z@W_msg[0:32], v = z@W_msg[32:64].
// Warp per node, lane = feature. Tail: fill rows [0, c1).
// ---------------------------------------------------------------------------
__global__ void k_encoder(const float* __restrict__ x, const float* __restrict__ h,
                          const float* __restrict__ W_enc, const float* __restrict__ b_enc,
                          const float* __restrict__ W_msg, int N,
                          float* __restrict__ p, int c1) {
    __shared__ float sWe[33 * HD];
    __shared__ float sWm[64 * HD];
    int tid = threadIdx.x;
    for (int i = tid; i < 33 * HD; i += blockDim.x) sWe[i] = W_enc[i];
    for (int i = tid; i < 64 * HD; i += blockDim.x) sWm[i] = W_msg[i];
    __syncthreads();

    int lane = tid & 31;
    int node = (int)((blockIdx.x * (size_t)blockDim.x + tid) >> 5);
    if (node < N) {
        float xn = x[node];
        float hl = h[node * HD + lane];
        float z0 = fmaf(xn, sWe[lane], b_enc[lane]);
        float z1 = 0.0f;
#pragma unroll
        for (int k = 0; k < HD; k += 2) {
            float hk0 = __shfl_sync(0xffffffffu, hl, k);
            float hk1 = __shfl_sync(0xffffffffu, hl, k + 1);
            z0 = fmaf(hk0, sWe[(1 + k) * HD + lane], z0);
            z1 = fmaf(hk1, sWe[(2 + k) * HD + lane], z1);
        }
        float z = z0 + z1;
        g_z[node * HD + lane] = z;

        float u = 0.0f, v = 0.0f;
#pragma unroll
        for (int k = 0; k < HD; k++) {
            float zk = __shfl_sync(0xffffffffu, z, k);
            u = fmaf(zk, sWm[k * HD + lane], u);
            v = fmaf(zk, sWm[(HD + k) * HD + lane], v);
        }
        g_u[node * HD + lane] = u;
        g_v[node * HD + lane] = v;
    }
    fill_rows(p, 0, c1, N);
}

// ---------------------------------------------------------------------------
// Update: segment-max over packed edge payload (8-wide MLP gathers) + decode
// + pred scalars + hsum. Warp per node. Last block (ticket) computes the
// termination scalar. Tail: fill rows [c1, c2).
// ---------------------------------------------------------------------------
__global__ void k_update(const float* __restrict__ W_msg, const float* __restrict__ b_msg,
                         const float* __restrict__ W_upd, const float* __restrict__ b_upd,
                         const float* __restrict__ W_dec, const float* __restrict__ b_dec,
                         const float* __restrict__ W_pred,
                         const float* __restrict__ W_term, const float* __restrict__ b_term,
                         float* __restrict__ out_y, float* __restrict__ out_h,
                         float* __restrict__ out_t, int N,
                         float* __restrict__ p, int c1, int c2) {
    __shared__ float sWu[64 * HD];
    __shared__ float red[8][HD];
    __shared__ int sIsLast;
    int tid = threadIdx.x;
    for (int i = tid; i < 64 * HD; i += blockDim.x) sWu[i] = W_upd[i];
    __syncthreads();

    int lane = tid & 31;
    int wip  = tid >> 5;
    int node = (int)((blockIdx.x * (size_t)blockDim.x + tid) >> 5);
    bool act = node < N;
    float hn = 0.0f;

    if (act) {
        float cw = W_msg[64 * HD + lane];
        int cnt = min(g_cnt[node], CAP);
        const int2* lst = &g_list[node * CAP];

        float mraw = __int_as_float(0xFF800000);  // -inf
        for (int base = 0; base < cnt; base += 32) {
            int nrem = min(32, cnt - base);
            int   myS = 0;
            float myW = 0.0f;
            if (lane < nrem) {
                int2 pk = lst[base + lane];   // ONE coalesced 256B load
                myS = pk.x;
                myW = __int_as_float(pk.y);
            }
            int k = 0;
            for (; k + 8 <= nrem; k += 8) {
                int s0 = __shfl_sync(0xffffffffu, myS, k);
                int s1 = __shfl_sync(0xffffffffu, myS, k + 1);
                int s2 = __shfl_sync(0xffffffffu, myS, k + 2);
                int s3 = __shfl_sync(0xffffffffu, myS, k + 3);
                int s4 = __shfl_sync(0xffffffffu, myS, k + 4);
                int s5 = __shfl_sync(0xffffffffu, myS, k + 5);
                int s6 = __shfl_sync(0xffffffffu, myS, k + 6);
                int s7 = __shfl_sync(0xffffffffu, myS, k + 7);
                float w0 = __shfl_sync(0xffffffffu, myW, k);
                float w1 = __shfl_sync(0xffffffffu, myW, k + 1);
                float w2 = __shfl_sync(0xffffffffu, myW, k + 2);
                float w3 = __shfl_sync(0xffffffffu, myW, k + 3);
                float w4 = __shfl_sync(0xffffffffu, myW, k + 4);
                float w5 = __shfl_sync(0xffffffffu, myW, k + 5);
                float w6 = __shfl_sync(0xffffffffu, myW, k + 6);
                float w7 = __shfl_sync(0xffffffffu, myW, k + 7);
                float v0 = g_v[s0 * HD + lane];   // 8 independent row gathers -> MLP 8
                float v1 = g_v[s1 * HD + lane];
                float v2 = g_v[s2 * HD + lane];
                float v3 = g_v[s3 * HD + lane];
                float v4 = g_v[s4 * HD + lane];
                float v5 = g_v[s5 * HD + lane];
                float v6 = g_v[s6 * HD + lane];
                float v7 = g_v[s7 * HD + lane];
                float a = fmaxf(fmaf(w0, cw, v0), fmaf(w1, cw, v1));
                float b = fmaxf(fmaf(w2, cw, v2), fmaf(w3, cw, v3));
                float c = fmaxf(fmaf(w4, cw, v4), fmaf(w5, cw, v5));
                float d = fmaxf(fmaf(w6, cw, v6), fmaf(w7, cw, v7));
                mraw = fmaxf(mraw, fmaxf(fmaxf(a, b), fmaxf(c, d)));
            }
            for (; k < nrem; k++) {
                int   sk = __shfl_sync(0xffffffffu, myS, k);
                float wk = __shfl_sync(0xffffffffu, myW, k);
                mraw = fmaxf(mraw, fmaf(wk, cw, g_v[sk * HD + lane]));
            }
        }

        float z = g_z[node * HD + lane];
        float m = (cnt == 0) ? 0.0f
                             : (g_u[node * HD + lane] + b_msg[lane] + mraw);

        float h0 = b_upd[lane], h1 = 0.0f;
#pragma unroll
        for (int k = 0; k < HD; k++) {
            float zk = __shfl_sync(0xffffffffu, z, k);
            float mk = __shfl_sync(0xffffffffu, m, k);
            h0 = fmaf(zk, sWu[k * HD + lane], h0);
            h1 = fmaf(mk, sWu[(HD + k) * HD + lane], h1);
        }
        hn = h0 + h1;
        out_h[node * HD + lane] = hn;

        float ry = fmaf(z, W_dec[lane], hn * W_dec[HD + lane]);
        float ra = hn * W_pred[lane];
        float rb = hn * W_pred[HD + lane];
#pragma unroll
        for (int o = 16; o > 0; o >>= 1) {
            ry += __shfl_xor_sync(0xffffffffu, ry, o);
            ra += __shfl_xor_sync(0xffffffffu, ra, o);
            rb += __shfl_xor_sync(0xffffffffu, rb, o);
        }
        if (lane == 0) {
            out_y[node] = ry + b_dec[0];
            g_pa[node] = ra;
            g_pb[node] = rb;
        }
    }

    red[wip][lane] = act ? hn : 0.0f;
    __syncthreads();
    if (wip == 0) {
        float s = red[0][lane];
#pragma unroll
        for (int j = 1; j < 8; j++) s += red[j][lane];
        atomicAdd(&g_hsum[lane], s);
    }

    // last-block ticket (same kernel -> all blocks guaranteed to run)
    __syncthreads();
    if (tid == 0) {
        __threadfence();
        int t = atomicAdd(&g_upd_ticket, 1);
        sIsLast = (t == (int)gridDim.x - 1);
    }
    __syncthreads();
    if (sIsLast) {
        if (tid < 32) {
            float v = (__ldcg(&g_hsum[tid]) / (float)N) * W_term[tid];
#pragma unroll
            for (int o = 16; o > 0; o >>= 1) v += __shfl_xor_sync(0xffffffffu, v, o);
            if (tid == 0) {
                out_t[0] = v + b_term[0];
                g_upd_ticket = 0;   // reset for next call
            }
        }
    }

    fill_rows(p, c1, c2, N);
}

// ---------------------------------------------------------------------------
// Final kernel: one block per row. Rows >= PRE: fill + scatter. Rows < PRE
// (already filled): scatter only. Resets g_cnt.
// ---------------------------------------------------------------------------
__global__ void __launch_bounds__(256)
k_rowfill(const float* __restrict__ W_pred, const float* __restrict__ b_pred,
          float* __restrict__ p, int N, int PRE) {
    int d = blockIdx.x;
    int tid = threadIdx.x;
    float* row = p + (size_t)d * N;

    if (d >= PRE) {
        int n4 = N >> 2;
        const float4 val = make_float4(-1e9f, -1e9f, -1e9f, -1e9f);
        float4* row4 = (float4*)row;
        for (int i = tid; i < n4; i += blockDim.x) __stcs(&row4[i], val);
        for (int i = (n4 << 2) + tid; i < N; i += blockDim.x) __stcs(&row[i], -1e9f);
        __syncthreads();   // row fully filled before edge overwrites
    }

    int cnt = min(g_cnt[d], CAP);
    if (tid < cnt) {
        float pa = g_pa[d];
        float c  = W_pred[64];
        float b0 = b_pred[0];
        for (int i = tid; i < cnt; i += blockDim.x) {
            int2 pk = g_list[d * CAP + i];
            int s = pk.x;
            row[s] = pa + g_pb[s] + fmaf(__int_as_float(pk.y), c, b0);
        }
    }
    if (tid == 0) g_cnt[d] = 0;   // reset for next call
}

// ---------------------------------------------------------------------------
extern "C" void kernel_launch(void* const* d_in, const int* in_sizes, int n_in,
                              void* d_out, int out_size) {
    const int*   sources = (const int*)d_in[0];
    const int*   dests   = (const int*)d_in[1];
    const float* weights = (const float*)d_in[2];
    const float* x       = (const float*)d_in[3];
    const float* h       = (const float*)d_in[4];
    const float* W_enc   = (const float*)d_in[5];
    const float* b_enc   = (const float*)d_in[6];
    const float* W_msg   = (const float*)d_in[7];
    const float* b_msg   = (const float*)d_in[8];
    const float* W_upd   = (const float*)d_in[9];
    const float* b_upd   = (const float*)d_in[10];
    const float* W_dec   = (const float*)d_in[11];
    const float* b_dec   = (const float*)d_in[12];
    const float* W_term  = (const float*)d_in[13];
    const float* b_term  = (const float*)d_in[14];
    const float* W_pred  = (const float*)d_in[15];
    const float* b_pred  = (const float*)d_in[16];

    int E = in_sizes[0];
    int N = in_sizes[3];  // x is (N, 1)

    float* out   = (float*)d_out;
    float* out_y = out;
    float* out_p = out + N;
    float* out_h = out + N + (size_t)N * N;
    float* out_t = out_h + (size_t)N * HD;

    int EB = (E + 255) / 256;
    int NB = (N * 32 + 255) / 256;

    // Fitted fill slices (fill time <= chain span at ~3.4TB/s mixed-mode BW):
    // encoder span ~12.5us -> 10% of rows; update span ~15us -> 12.5% of rows.
    int c1 = N / 10;                 // encoder fills [0, 10%)
    int c2 = c1 + N / 8;             // update fills [10%, 22.5%)

    k_build<<<EB, 256>>>(dests, sources, weights, E);
    k_encoder<<<NB, 256>>>(x, h, W_enc, b_enc, W_msg, N, out_p, c1);
    k_update<<<NB, 256>>>(W_msg, b_msg, W_upd, b_upd,
                          W_dec, b_dec, W_pred, W_term, b_term,
                          out_y, out_h, out_t, N, out_p, c1, c2);
    k_rowfill<<<N, 256>>>(W_pred, b_pred, out_p, N, c2);
}

// round 16
// speedup vs baseline: 1.0589x; 1.0208x over previous
#include <cuda_runtime.h>
#include <math.h>
#include <stdint.h>

#define HD 32
#define MAXN 10000
#define CAP 256      // max in-degree supported (E/N = 32 mean; Poisson tail << 256)

// Scratch (device globals — no allocation allowed; zero-initialized at load)
__device__ float g_z[MAXN * HD];
__device__ float g_u[MAXN * HD];
__device__ float g_v[MAXN * HD];
__device__ float g_pa[MAXN];
__device__ float g_pb[MAXN];
__device__ float g_hsum[HD];
__device__ int   g_cnt[MAXN];     // zero at load; reset by k_rowfill each call
__device__ int2  g_list[MAXN * CAP];   // packed edge payload: {source, weight_bits}
__device__ int   g_upd_ticket;    // single-kernel ticket; reset by last update block

// ---------------------------------------------------------------------------
// Streaming fill of rows [rowBeg, rowEnd) of p with -1e9, distributed over a
// SUBSET of blocks (roleIdx in [0, roleCount)). Called from kernel tails;
// slices sized so fill time fits within the role's chain span.
// ---------------------------------------------------------------------------
__device__ __forceinline__ void fill_rows_sub(float* __restrict__ p, int rowBeg, int rowEnd,
                                              int N, int roleIdx, int roleCount) {
    if (rowEnd <= rowBeg) return;
    size_t stride = (size_t)roleCount * blockDim.x;
    size_t start  = (size_t)roleIdx * blockDim.x + threadIdx.x;
    size_t nflt   = (size_t)(rowEnd - rowBeg) * (size_t)N;
    float* base   = p + (size_t)rowBeg * (size_t)N;
    if ((N & 3) == 0) {
        const float4 val = make_float4(-1e9f, -1e9f, -1e9f, -1e9f);
        float4* p4 = (float4*)base;
        size_t n4 = nflt >> 2;
        for (size_t i = start; i < n4; i += stride) __stcs(&p4[i], val);
    } else {
        for (size_t i = start; i < nflt; i += stride) __stcs(&base[i], -1e9f);
    }
}

// ---------------------------------------------------------------------------
// Merged kernel 1: blocks [0, EB) build the packed per-dest edge lists
// (then fill rows [0, cA)); blocks [EB, EB+NB) run the encoder
// (then fill rows [cA, cB)). Build and encoder are mutually independent.
// ---------------------------------------------------------------------------
__global__ void k_build_enc(const int* __restrict__ dests, const int* __restrict__ sources,
                            const float* __restrict__ weights, int E,
                            const float* __restrict__ x, const float* __restrict__ h,
                            const float* __restrict__ W_enc, const float* __restrict__ b_enc,
                            const float* __restrict__ W_msg, int N,
                            float* __restrict__ p, int cA, int cB, int EB, int NB) {
    int tid = threadIdx.x;

    if ((int)blockIdx.x < EB) {
        // ---- build role ----
        if (blockIdx.x == 0 && tid < HD) g_hsum[tid] = 0.0f;
        int e = blockIdx.x * blockDim.x + tid;
        if (e < E) {
            int d = dests[e];
            int s = sources[e];                 // coalesced
            float w = weights[e];               // coalesced
            int slot = atomicAdd(&g_cnt[d], 1);
            if (slot < CAP) g_list[d * CAP + slot] = make_int2(s, __float_as_int(w));
        }
        fill_rows_sub(p, 0, cA, N, blockIdx.x, EB);
        return;
    }

    // ---- encoder role ----
    __shared__ float sWe[33 * HD];
    __shared__ float sWm[64 * HD];
    for (int i = tid; i < 33 * HD; i += blockDim.x) sWe[i] = W_enc[i];
    for (int i = tid; i < 64 * HD; i += blockDim.x) sWm[i] = W_msg[i];
    __syncthreads();

    int lane = tid & 31;
    int node = (int)(((blockIdx.x - EB) * (size_t)blockDim.x + tid) >> 5);
    if (node < N) {
        float xn = x[node];
        float hl = h[node * HD + lane];
        float z0 = fmaf(xn, sWe[lane], b_enc[lane]);
        float z1 = 0.0f;
#pragma unroll
        for (int k = 0; k < HD; k += 2) {
            float hk0 = __shfl_sync(0xffffffffu, hl, k);
            float hk1 = __shfl_sync(0xffffffffu, hl, k + 1);
            z0 = fmaf(hk0, sWe[(1 + k) * HD + lane], z0);
            z1 = fmaf(hk1, sWe[(2 + k) * HD + lane], z1);
        }
        float z = z0 + z1;
        g_z[node * HD + lane] = z;

        float u = 0.0f, v = 0.0f;
#pragma unroll
        for (int k = 0; k < HD; k++) {
            float zk = __shfl_sync(0xffffffffu, z, k);
            u = fmaf(zk, sWm[k * HD + lane], u);
            v = fmaf(zk, sWm[(HD + k) * HD + lane], v);
        }
        g_u[node * HD + lane] = u;
        g_v[node * HD + lane] = v;
    }
    fill_rows_sub(p, cA, cB, N, blockIdx.x - EB, NB);
}

// ---------------------------------------------------------------------------
// Update: segment-max over packed edge payload (8-wide MLP gathers) + decode
// + pred scalars + hsum. Warp per node. Last block (ticket) computes the
// termination scalar. Tail: fill rows [cB, cC).
// ---------------------------------------------------------------------------
__global__ void k_update(const float* __restrict__ W_msg, const float* __restrict__ b_msg,
                         const float* __restrict__ W_upd, const float* __restrict__ b_upd,
                         const float* __restrict__ W_dec, const float* __restrict__ b_dec,
                         const float* __restrict__ W_pred,
                         const float* __restrict__ W_term, const float* __restrict__ b_term,
                         float* __restrict__ out_y, float* __restrict__ out_h,
                         float* __restrict__ out_t, int N,
                         float* __restrict__ p, int cB, int cC) {
    __shared__ float sWu[64 * HD];
    __shared__ float red[8][HD];
    __shared__ int sIsLast;
    int tid = threadIdx.x;
    for (int i = tid; i < 64 * HD; i += blockDim.x) sWu[i] = W_upd[i];
    __syncthreads();

    int lane = tid & 31;
    int wip  = tid >> 5;
    int node = (int)((blockIdx.x * (size_t)blockDim.x + tid) >> 5);
    bool act = node < N;
    float hn = 0.0f;

    if (act) {
        float cw = W_msg[64 * HD + lane];
        int cnt = min(g_cnt[node], CAP);
        const int2* lst = &g_list[node * CAP];

        float mraw = __int_as_float(0xFF800000);  // -inf
        for (int base = 0; base < cnt; base += 32) {
            int nrem = min(32, cnt - base);
            int   myS = 0;
            float myW = 0.0f;
            if (lane < nrem) {
                int2 pk = lst[base + lane];   // ONE coalesced 256B load
                myS = pk.x;
                myW = __int_as_float(pk.y);
            }
            int k = 0;
            for (; k + 8 <= nrem; k += 8) {
                int s0 = __shfl_sync(0xffffffffu, myS, k);
                int s1 = __shfl_sync(0xffffffffu, myS, k + 1);
                int s2 = __shfl_sync(0xffffffffu, myS, k + 2);
                int s3 = __shfl_sync(0xffffffffu, myS, k + 3);
                int s4 = __shfl_sync(0xffffffffu, myS, k + 4);
                int s5 = __shfl_sync(0xffffffffu, myS, k + 5);
                int s6 = __shfl_sync(0xffffffffu, myS, k + 6);
                int s7 = __shfl_sync(0xffffffffu, myS, k + 7);
                float w0 = __shfl_sync(0xffffffffu, myW, k);
                float w1 = __shfl_sync(0xffffffffu, myW, k + 1);
                float w2 = __shfl_sync(0xffffffffu, myW, k + 2);
                float w3 = __shfl_sync(0xffffffffu, myW, k + 3);
                float w4 = __shfl_sync(0xffffffffu, myW, k + 4);
                float w5 = __shfl_sync(0xffffffffu, myW, k + 5);
                float w6 = __shfl_sync(0xffffffffu, myW, k + 6);
                float w7 = __shfl_sync(0xffffffffu, myW, k + 7);
                float v0 = g_v[s0 * HD + lane];   // 8 independent row gathers -> MLP 8
                float v1 = g_v[s1 * HD + lane];
                float v2 = g_v[s2 * HD + lane];
                float v3 = g_v[s3 * HD + lane];
                float v4 = g_v[s4 * HD + lane];
                float v5 = g_v[s5 * HD + lane];
                float v6 = g_v[s6 * HD + lane];
                float v7 = g_v[s7 * HD + lane];
                float a = fmaxf(fmaf(w0, cw, v0), fmaf(w1, cw, v1));
                float b = fmaxf(fmaf(w2, cw, v2), fmaf(w3, cw, v3));
                float c = fmaxf(fmaf(w4, cw, v4), fmaf(w5, cw, v5));
                float d = fmaxf(fmaf(w6, cw, v6), fmaf(w7, cw, v7));
                mraw = fmaxf(mraw, fmaxf(fmaxf(a, b), fmaxf(c, d)));
            }
            for (; k < nrem; k++) {
                int   sk = __shfl_sync(0xffffffffu, myS, k);
                float wk = __shfl_sync(0xffffffffu, myW, k);
                mraw = fmaxf(mraw, fmaf(wk, cw, g_v[sk * HD + lane]));
            }
        }

        float z = g_z[node * HD + lane];
        float m = (cnt == 0) ? 0.0f
                             : (g_u[node * HD + lane] + b_msg[lane] + mraw);

        float h0 = b_upd[lane], h1 = 0.0f;
#pragma unroll
        for (int k = 0; k < HD; k++) {
            float zk = __shfl_sync(0xffffffffu, z, k);
            float mk = __shfl_sync(0xffffffffu, m, k);
            h0 = fmaf(zk, sWu[k * HD + lane], h0);
            h1 = fmaf(mk, sWu[(HD + k) * HD + lane], h1);
        }
        hn = h0 + h1;
        out_h[node * HD + lane] = hn;

        float ry = fmaf(z, W_dec[lane], hn * W_dec[HD + lane]);
        float ra = hn * W_pred[lane];
        float rb = hn * W_pred[HD + lane];
#pragma unroll
        for (int o = 16; o > 0; o >>= 1) {
            ry += __shfl_xor_sync(0xffffffffu, ry, o);
            ra += __shfl_xor_sync(0xffffffffu, ra, o);
            rb += __shfl_xor_sync(0xffffffffu, rb, o);
        }
        if (lane == 0) {
            out_y[node] = ry + b_dec[0];
            g_pa[node] = ra;
            g_pb[node] = rb;
        }
    }

    red[wip][lane] = act ? hn : 0.0f;
    __syncthreads();
    if (wip == 0) {
        float s = red[0][lane];
#pragma unroll
        for (int j = 1; j < 8; j++) s += red[j][lane];
        atomicAdd(&g_hsum[lane], s);
    }

    // last-block ticket (same kernel -> all blocks guaranteed to run)
    __syncthreads();
    if (tid == 0) {
        __threadfence();
        int t = atomicAdd(&g_upd_ticket, 1);
        sIsLast = (t == (int)gridDim.x - 1);
    }
    __syncthreads();
    if (sIsLast) {
        if (tid < 32) {
            float v = (__ldcg(&g_hsum[tid]) / (float)N) * W_term[tid];
#pragma unroll
            for (int o = 16; o > 0; o >>= 1) v += __shfl_xor_sync(0xffffffffu, v, o);
            if (tid == 0) {
                out_t[0] = v + b_term[0];
                g_upd_ticket = 0;   // reset for next call
            }
        }
    }

    fill_rows_sub(p, cB, cC, N, blockIdx.x, gridDim.x);
}

// ---------------------------------------------------------------------------
// Final kernel: one block per row. Rows >= PRE: fill + scatter. Rows < PRE
// (already filled): scatter only. Resets g_cnt.
// ---------------------------------------------------------------------------
__global__ void __launch_bounds__(256)
k_rowfill(const float* __restrict__ W_pred, const float* __restrict__ b_pred,
          float* __restrict__ p, int N, int PRE) {
    int d = blockIdx.x;
    int tid = threadIdx.x;
    float* row = p + (size_t)d * N;

    if (d >= PRE) {
        int n4 = N >> 2;
        const float4 val = make_float4(-1e9f, -1e9f, -1e9f, -1e9f);
        float4* row4 = (float4*)row;
        for (int i = tid; i < n4; i += blockDim.x) __stcs(&row4[i], val);
        for (int i = (n4 << 2) + tid; i < N; i += blockDim.x) __stcs(&row[i], -1e9f);
        __syncthreads();   // row fully filled before edge overwrites
    }

    int cnt = min(g_cnt[d], CAP);
    if (tid < cnt) {
        float pa = g_pa[d];
        float c  = W_pred[64];
        float b0 = b_pred[0];
        for (int i = tid; i < cnt; i += blockDim.x) {
            int2 pk = g_list[d * CAP + i];
            int s = pk.x;
            row[s] = pa + g_pb[s] + fmaf(__int_as_float(pk.y), c, b0);
        }
    }
    if (tid == 0) g_cnt[d] = 0;   // reset for next call
}

// ---------------------------------------------------------------------------
extern "C" void kernel_launch(void* const* d_in, const int* in_sizes, int n_in,
                              void* d_out, int out_size) {
    const int*   sources = (const int*)d_in[0];
    const int*   dests   = (const int*)d_in[1];
    const float* weights = (const float*)d_in[2];
    const float* x       = (const float*)d_in[3];
    const float* h       = (const float*)d_in[4];
    const float* W_enc   = (const float*)d_in[5];
    const float* b_enc   = (const float*)d_in[6];
    const float* W_msg   = (const float*)d_in[7];
    const float* b_msg   = (const float*)d_in[8];
    const float* W_upd   = (const float*)d_in[9];
    const float* b_upd   = (const float*)d_in[10];
    const float* W_dec   = (const float*)d_in[11];
    const float* b_dec   = (const float*)d_in[12];
    const float* W_term  = (const float*)d_in[13];
    const float* b_term  = (const float*)d_in[14];
    const float* W_pred  = (const float*)d_in[15];
    const float* b_pred  = (const float*)d_in[16];

    int E = in_sizes[0];
    int N = in_sizes[3];  // x is (N, 1)

    float* out   = (float*)d_out;
    float* out_y = out;
    float* out_p = out + N;
    float* out_h = out + N + (size_t)N * N;
    float* out_t = out_h + (size_t)N * HD;

    int EB = (E + 255) / 256;
    int NB = (N * 32 + 255) / 256;

    // Fitted fill slices (fill time <= role span at ~3.4TB/s mixed-mode BW):
    // build role ~5us span -> 3% of rows; encoder ~12.5us -> 10%; update ~15us -> 12.5%.
    int cA = (N * 3) / 100;          // build blocks fill [0, 3%)
    int cB = cA + N / 10;            // encoder blocks fill [3%, 13%)
    int cC = cB + N / 8;             // update fills [13%, 25.5%)

    k_build_enc<<<EB + NB, 256>>>(dests, sources, weights, E,
                                  x, h, W_enc, b_enc, W_msg, N,
                                  out_p, cA, cB, EB, NB);
    k_update<<<NB, 256>>>(W_msg, b_msg, W_upd, b_upd,
                          W_dec, b_dec, W_pred, W_term, b_term,
                          out_y, out_h, out_t, N, out_p, cB, cC);
    k_rowfill<<<N, 256>>>(W_pred, b_pred, out_p, N, cC);
}